// round 13
// baseline (speedup 1.0000x reference)
#include <cuda_runtime.h>
#include <cuda_fp16.h>
#include <math.h>
#include <stdint.h>

#define NTOK 64
#define DIM 512
#define HEADS 8
#define NB 2048
#define MROWS (NB * NTOK)   // 131072
#define SCALE 0.125f
#define KDIM 512

// ---------------- scratch (device globals; no allocation) ----------------
static __device__ __half g_qkvh[(size_t)MROWS * 1536];  // q(scaled)|k|v  (half)
static __device__ float  g_mult[(size_t)NB * NTOK * NTOK];
static __device__ __half g_oh[(size_t)MROWS * DIM];     // attn out (half)
static __device__ __half g_xh[(size_t)MROWS * DIM];     // x  (half)
static __device__ __half g_wh[(size_t)2048 * 512];      // wq*SCALE|wkv|wproj (half)
static __device__ float  g_bias[1536];                  // SCALE*bq | bkv

__device__ __forceinline__ uint32_t smem_u32(const void* p) {
    uint32_t a;
    asm("{ .reg .u64 t; cvta.to.shared.u64 t, %1; cvt.u32.u64 %0, t; }" : "=r"(a) : "l"(p));
    return a;
}
#define CP_ASYNC16(dst, src) \
    asm volatile("cp.async.cg.shared.global [%0], [%1], 16;" :: "r"(dst), "l"(src) : "memory")
#define CP_COMMIT() asm volatile("cp.async.commit_group;" ::: "memory")
#define CP_WAIT2()  asm volatile("cp.async.wait_group 2;" ::: "memory")
#define CP_WAIT0()  asm volatile("cp.async.wait_group 0;" ::: "memory")

#define LDSM_X4(r0, r1, r2, r3, a) \
    asm volatile("ldmatrix.sync.aligned.m8n8.x4.shared.b16 {%0,%1,%2,%3}, [%4];" \
                 : "=r"(r0), "=r"(r1), "=r"(r2), "=r"(r3) : "r"(a))
#define LDSM_X2T(r0, r1, a) \
    asm volatile("ldmatrix.sync.aligned.m8n8.x2.trans.shared.b16 {%0,%1}, [%2];" \
                 : "=r"(r0), "=r"(r1) : "r"(a))

__device__ __forceinline__ void mma_f16(float* d, const uint32_t* a, const uint32_t* b) {
    asm volatile(
        "mma.sync.aligned.m16n8k16.row.col.f32.f16.f16.f32 "
        "{%0,%1,%2,%3}, {%4,%5,%6,%7}, {%8,%9}, {%0,%1,%2,%3};"
        : "+f"(d[0]), "+f"(d[1]), "+f"(d[2]), "+f"(d[3])
        : "r"(a[0]), "r"(a[1]), "r"(a[2]), "r"(a[3]), "r"(b[0]), "r"(b[1]));
}

// ===================== conversions =====================
__global__ void conv_kernel(const float* __restrict__ in, __half* __restrict__ out, int n4)
{
    int i = blockIdx.x * blockDim.x + threadIdx.x;
    int stride = gridDim.x * blockDim.x;
    for (; i < n4; i += stride) {
        float4 v = ((const float4*)in)[i];
        __half2* o = (__half2*)out;
        o[2 * i]     = __floats2half2_rn(v.x, v.y);
        o[2 * i + 1] = __floats2half2_rn(v.z, v.w);
    }
}

__global__ void wconv_kernel(const float* __restrict__ wq, const float* __restrict__ wkv,
                             const float* __restrict__ wproj, const float* __restrict__ bq,
                             const float* __restrict__ bkv, float* __restrict__ gb,
                             __half* __restrict__ wh)
{
    int i = blockIdx.x * blockDim.x + threadIdx.x;
    float s = 1.0f;
    const float* src;
    int o;
    if (i < 65536)       { src = wq;    o = i;          s = SCALE; }
    else if (i < 196608) { src = wkv;   o = i - 65536; }
    else                 { src = wproj; o = i - 196608; }
    float4 v = ((const float4*)src)[o];
    __half2* out = (__half2*)wh;
    out[2 * i]     = __floats2half2_rn(v.x * s, v.y * s);
    out[2 * i + 1] = __floats2half2_rn(v.z * s, v.w * s);
    if (i < 384) {
        float4 bv;
        if (i < 128) {
            bv = ((const float4*)bq)[i];
            bv.x *= SCALE; bv.y *= SCALE; bv.z *= SCALE; bv.w *= SCALE;
        } else {
            bv = ((const float4*)bkv)[i - 128];
        }
        ((float4*)gb)[i] = bv;
    }
}

// =====================================================================
// fp16 mma GEMM with ldmatrix fragment loads: C = A @ B^T + bias
// =====================================================================
#define BKH 64
#define HSTRIDE 72
#define STAGE_HALFS ((128 + 256) * HSTRIDE)
#define STAGE_BYTES (STAGE_HALFS * 2)
#define NSTAGE 3
#define SMEM_GEMM_BYTES (NSTAGE * STAGE_BYTES)
#define NCHUNK (KDIM / BKH)

template<int OUTH>
__global__ __launch_bounds__(256, 1)
void gemm_f16(const __half* __restrict__ A, const __half* __restrict__ B,
              const float* __restrict__ bias, void* __restrict__ Cv, long ldc)
{
    extern __shared__ char smc[];
    __half* smh = (__half*)smc;
    const int tid = threadIdx.x;
    const int lane = tid & 31;
    const int wid = tid >> 5;
    const int warp_m = wid & 1;
    const int warp_n = wid >> 1;
    const long m0 = (long)blockIdx.y * 128;
    const long n0 = (long)blockIdx.x * 256;

    const __half* Ag = A + m0 * KDIM;
    const __half* Bg = B + n0 * KDIM;
    const uint32_t sb = smem_u32(smc);

    auto copy_chunk = [&](int chunk, int s) {
        const int k0 = chunk * BKH;
        const uint32_t dstA = sb + s * STAGE_BYTES;
        const uint32_t dstB = dstA + 128 * HSTRIDE * 2;
#pragma unroll
        for (int i = 0; i < 4; i++) {
            int idx = tid + i * 256;
            int row = idx >> 3, q = idx & 7;
            CP_ASYNC16(dstA + row * (HSTRIDE * 2) + q * 16,
                       Ag + (long)row * KDIM + k0 + q * 8);
        }
#pragma unroll
        for (int i = 0; i < 8; i++) {
            int idx = tid + i * 256;
            int row = idx >> 3, q = idx & 7;
            CP_ASYNC16(dstB + row * (HSTRIDE * 2) + q * 16,
                       Bg + (long)row * KDIM + k0 + q * 8);
        }
        CP_COMMIT();
    };

    float acc[4][8][4];
#pragma unroll
    for (int mt = 0; mt < 4; mt++)
#pragma unroll
        for (int nt = 0; nt < 8; nt++)
#pragma unroll
            for (int e = 0; e < 4; e++) acc[mt][nt][e] = 0.f;

    copy_chunk(0, 0);
    copy_chunk(1, 1);
    copy_chunk(2, 2);

    const int r = lane >> 2;
    const int cc = lane & 3;
    const uint32_t aOff = ((warp_m * 64 + (lane & 15)) * HSTRIDE) * 2 + (lane >> 4) * 16;
    const uint32_t bOff = 128 * HSTRIDE * 2 +
        ((warp_n * 64 + ((lane >> 4) << 3) + (lane & 7)) * HSTRIDE) * 2 + ((lane >> 3) & 1) * 16;

    for (int c = 0; c < NCHUNK; c++) {
        const int s = c % NSTAGE;
        CP_WAIT2();
        __syncthreads();
        const uint32_t stA = sb + s * STAGE_BYTES;
        const uint32_t aL = stA + aOff;
        const uint32_t bL = stA + bOff;

#pragma unroll
        for (int k16 = 0; k16 < 4; k16++) {
            uint32_t af[4][4], bf[8][2];
#pragma unroll
            for (int mt = 0; mt < 4; mt++)
                LDSM_X4(af[mt][0], af[mt][1], af[mt][2], af[mt][3],
                        aL + mt * 16 * HSTRIDE * 2 + k16 * 32);
#pragma unroll
            for (int p = 0; p < 4; p++) {
                uint32_t r0, r1, r2, r3;
                LDSM_X4(r0, r1, r2, r3, bL + p * 16 * HSTRIDE * 2 + k16 * 32);
                bf[2 * p][0] = r0;     bf[2 * p][1] = r1;
                bf[2 * p + 1][0] = r2; bf[2 * p + 1][1] = r3;
            }
#pragma unroll
            for (int mt = 0; mt < 4; mt++)
#pragma unroll
                for (int nt = 0; nt < 8; nt++)
                    mma_f16(acc[mt][nt], af[mt], bf[nt]);
        }
        __syncthreads();
        if (c + 3 < NCHUNK) copy_chunk(c + 3, s);
        else CP_COMMIT();
    }

    if (OUTH) {
        __half* se = smh;
        const int row0 = warp_m * 64;
        const int col0 = warp_n * 64;
#pragma unroll
        for (int mt = 0; mt < 4; mt++)
#pragma unroll
            for (int nt = 0; nt < 8; nt++) {
                int rr = row0 + mt * 16 + r;
                int cb = col0 + nt * 8 + 2 * cc;
                float2 bv = *(const float2*)(bias + n0 + cb);
                *(__half2*)(se + rr * 264 + cb) =
                    __floats2half2_rn(acc[mt][nt][0] + bv.x, acc[mt][nt][1] + bv.y);
                *(__half2*)(se + (rr + 8) * 264 + cb) =
                    __floats2half2_rn(acc[mt][nt][2] + bv.x, acc[mt][nt][3] + bv.y);
            }
        __syncthreads();
        __half* Ch = (__half*)Cv;
#pragma unroll
        for (int i = 0; i < 16; i++) {
            int idx = tid + i * 256;
            int row = idx >> 5;
            int c8 = (idx & 31) * 8;
            float4 v = *(const float4*)(se + row * 264 + c8);
            *(float4*)(Ch + (m0 + row) * ldc + n0 + c8) = v;
        }
    } else {
        float* se = (float*)smc;
        const int row0 = warp_m * 64;
        const int col0 = warp_n * 64;
#pragma unroll
        for (int mt = 0; mt < 4; mt++)
#pragma unroll
            for (int nt = 0; nt < 8; nt++) {
                int rr = row0 + mt * 16 + r;
                int cb = col0 + nt * 8 + 2 * cc;
                float2 bv = *(const float2*)(bias + n0 + cb);
                *(float2*)(se + rr * 264 + cb) =
                    make_float2(acc[mt][nt][0] + bv.x, acc[mt][nt][1] + bv.y);
                *(float2*)(se + (rr + 8) * 264 + cb) =
                    make_float2(acc[mt][nt][2] + bv.x, acc[mt][nt][3] + bv.y);
            }
        __syncthreads();
        float* Cf = (float*)Cv;
#pragma unroll
        for (int i = 0; i < 32; i++) {
            int idx = tid + i * 256;
            int row = idx >> 6;
            int c4 = (idx & 63) * 4;
            float4 v = *(const float4*)(se + row * 264 + c4);
            *(float4*)(Cf + (m0 + row) * ldc + n0 + c4) = v;
        }
    }
}

// =====================================================================
// Correlation-map kernel: three Grams via fp16 mma (+ __expf plane map)
// =====================================================================
#define MH_STRIDE 104
#define MK_D   0
#define MK_G   (MK_D + 26624)
#define MK_G2  (MK_G + 17408)
#define MK_SF  (MK_G2 + 17408)
#define MK_SCL (MK_SF + 3072)
#define MK_RND (MK_SCL + 3072)
#define MK_RNS (MK_RND + 256)
#define MK_SP  (MK_RNS + 256)
#define MK_SN  (MK_SP + 768)
#define MK_SC  (MK_SN + 768)
#define SMEM_MULT_BYTES (MK_SC + 256)

__global__ __launch_bounds__(256)
void mult_kernel(const float* __restrict__ dino, const float* __restrict__ point,
                 const float* __restrict__ sdf, const float* __restrict__ normal,
                 const float* __restrict__ smask, const float* __restrict__ cmask,
                 float* __restrict__ mout)
{
    extern __shared__ char smc[];
    __half* sDh  = (__half*)(smc + MK_D);
    float* sG3   = (float*)(smc + MK_D);
    float* sG    = (float*)(smc + MK_G);
    float* sG2   = (float*)(smc + MK_G2);
    __half* sfh  = (__half*)(smc + MK_SF);
    __half* sclh = (__half*)(smc + MK_SCL);
    float* rnD   = (float*)(smc + MK_RND);
    float* rnS   = (float*)(smc + MK_RNS);
    float* sp    = (float*)(smc + MK_SP);
    float* sn    = (float*)(smc + MK_SN);
    float* scode = (float*)(smc + MK_SC);

    const int b = blockIdx.x;
    const int tid = threadIdx.x;
    const int lane = tid & 31, w = tid >> 5;
    const int r = lane >> 2, cc = lane & 3;
    const int m0 = (w & 3) * 16, n0 = (w >> 2) * 32;

    {
        int row = tid >> 2;
        int kg = (tid & 3) * 4;
        float4 v = *(const float4*)(sdf + (size_t)b * 1024 + row * 16 + kg);
        *(__half2*)(sfh + row * 24 + kg)     = __floats2half2_rn(v.x, v.y);
        *(__half2*)(sfh + row * 24 + kg + 2) = __floats2half2_rn(v.z, v.w);
    }
    if (tid < 128) {
        int row = tid >> 1;
        int c4 = (tid & 1) * 4;
        float4 v = *(const float4*)(cmask + (size_t)b * 512 + row * 8 + c4);
        *(__half2*)(sclh + row * 24 + c4)     = __floats2half2_rn(v.x, v.y);
        *(__half2*)(sclh + row * 24 + c4 + 2) = __floats2half2_rn(v.z, v.w);
        *(uint2*)(sclh + row * 24 + 8 + c4) = make_uint2(0u, 0u);
    }
    if (tid < 192) {
        sp[tid] = point[(size_t)b * 192 + tid];
        sn[tid] = normal[(size_t)b * 192 + tid];
    }
    if (tid < 64)
        scode[tid] = (smask[(size_t)b * 64 + tid] < 0.1f) ? 1.f : 2.f;

    const float* dg = dino + (size_t)b * 64 * 384;
    auto load_chunk = [&](int kc, int buf) {
        __half* dst = sDh + buf * 64 * MH_STRIDE;
        const int k0 = kc * 96;
#pragma unroll
        for (int i = 0; i < 6; i++) {
            int idx = tid + i * 256;
            int row = idx / 24;
            int q = idx % 24;
            float4 v = *(const float4*)(dg + row * 384 + k0 + q * 4);
            *(__half2*)(dst + row * MH_STRIDE + q * 4)     = __floats2half2_rn(v.x, v.y);
            *(__half2*)(dst + row * MH_STRIDE + q * 4 + 2) = __floats2half2_rn(v.z, v.w);
        }
    };

    float gacc[4][4];
#pragma unroll
    for (int i = 0; i < 4; i++)
#pragma unroll
        for (int j = 0; j < 4; j++) gacc[i][j] = 0.f;

    load_chunk(0, 0);
    __syncthreads();
    for (int c = 0; c < 4; c++) {
        if (c + 1 < 4) load_chunk(c + 1, (c + 1) & 1);
        const __half* buf = sDh + (c & 1) * 64 * MH_STRIDE;
        const __half* aB = buf + (m0 + r) * MH_STRIDE + 2 * cc;
#pragma unroll
        for (int ks = 0; ks < 6; ks++) {
            uint32_t af[4];
            const __half* ap = aB + ks * 16;
            af[0] = *(const uint32_t*)(ap);
            af[1] = *(const uint32_t*)(ap + 8 * MH_STRIDE);
            af[2] = *(const uint32_t*)(ap + 8);
            af[3] = *(const uint32_t*)(ap + 8 * MH_STRIDE + 8);
#pragma unroll
            for (int nt = 0; nt < 4; nt++) {
                const __half* bp = buf + (n0 + nt * 8 + r) * MH_STRIDE + 2 * cc + ks * 16;
                uint32_t bf[2] = { *(const uint32_t*)(bp), *(const uint32_t*)(bp + 8) };
                mma_f16(gacc[nt], af, bf);
            }
        }
        __syncthreads();
    }

    float s2[4][4], s3[4][4];
#pragma unroll
    for (int i = 0; i < 4; i++)
#pragma unroll
        for (int j = 0; j < 4; j++) { s2[i][j] = 0.f; s3[i][j] = 0.f; }
    {
        const __half* ap2 = sfh + (m0 + r) * 24 + 2 * cc;
        uint32_t af2[4] = { *(const uint32_t*)(ap2), *(const uint32_t*)(ap2 + 8 * 24),
                            *(const uint32_t*)(ap2 + 8), *(const uint32_t*)(ap2 + 8 * 24 + 8) };
        const __half* ap3 = sclh + (m0 + r) * 24 + 2 * cc;
        uint32_t af3[4] = { *(const uint32_t*)(ap3), *(const uint32_t*)(ap3 + 8 * 24),
                            *(const uint32_t*)(ap3 + 8), *(const uint32_t*)(ap3 + 8 * 24 + 8) };
#pragma unroll
        for (int nt = 0; nt < 4; nt++) {
            const __half* bp2 = sfh + (n0 + nt * 8 + r) * 24 + 2 * cc;
            uint32_t bf2[2] = { *(const uint32_t*)(bp2), *(const uint32_t*)(bp2 + 8) };
            mma_f16(s2[nt], af2, bf2);
            const __half* bp3 = sclh + (n0 + nt * 8 + r) * 24 + 2 * cc;
            uint32_t bf3[2] = { *(const uint32_t*)(bp3), *(const uint32_t*)(bp3 + 8) };
            mma_f16(s3[nt], af3, bf3);
        }
    }

#pragma unroll
    for (int nt = 0; nt < 4; nt++) {
        int col = n0 + nt * 8 + 2 * cc;
        int I0 = m0 + r, I1 = I0 + 8;
        sG[I0 * 68 + col]      = gacc[nt][0];
        sG[I0 * 68 + col + 1]  = gacc[nt][1];
        sG[I1 * 68 + col]      = gacc[nt][2];
        sG[I1 * 68 + col + 1]  = gacc[nt][3];
        sG2[I0 * 68 + col]     = s2[nt][0];
        sG2[I0 * 68 + col + 1] = s2[nt][1];
        sG2[I1 * 68 + col]     = s2[nt][2];
        sG2[I1 * 68 + col + 1] = s2[nt][3];
        sG3[I0 * 68 + col]     = s3[nt][0];
        sG3[I0 * 68 + col + 1] = s3[nt][1];
        sG3[I1 * 68 + col]     = s3[nt][2];
        sG3[I1 * 68 + col + 1] = s3[nt][3];
    }
    __syncthreads();

    if (tid < 64) {
        float nn = fminf(fmaxf(sqrtf(fmaxf(sG[tid * 68 + tid], 0.f)), 1e-20f), 1e10f);
        rnD[tid] = 1.0f / nn;
        nn = fminf(fmaxf(sqrtf(fmaxf(sG2[tid * 68 + tid], 0.f)), 1e-20f), 1e10f);
        rnS[tid] = 1.0f / nn;
    }
    __syncthreads();

    const int tx = tid & 15, ty = tid >> 4;
    float* mrow = mout + (size_t)b * 4096;
#pragma unroll
    for (int i = 0; i < 4; i++) {
        int I = ty * 4 + i;
        float ga[4], g2a[4], g3a[4], res[4];
        *(float4*)ga  = *(const float4*)(sG  + I * 68 + tx * 4);
        *(float4*)g2a = *(const float4*)(sG2 + I * 68 + tx * 4);
        *(float4*)g3a = *(const float4*)(sG3 + I * 68 + tx * 4);
#pragma unroll
        for (int j = 0; j < 4; j++) {
            int J = tx * 4 + j;
            float dmap = fminf(fmaxf(ga[j] * rnD[I] * rnD[J], 0.f), 1e10f);
            float smap = 1.f - fminf(fmaxf(g2a[j] * rnS[I] * rnS[J], 0.f), 1.f);
            float P1 = 0.f, P2 = 0.f;
#pragma unroll
            for (int d = 0; d < 3; d++) {
                float diff = sp[I * 3 + d] - sp[J * 3 + d];
                P1 += diff * sn[I * 3 + d];
                P2 += diff * sn[J * 3 + d];
            }
            float plane = __expf(-0.5f * (fabsf(P1) + fabsf(P2)));
            float mm = (scode[I] * scode[J] == 2.f) ? 1.f : 0.2f;
            res[j] = dmap * smap * plane * g3a[j] * mm;
        }
        *(float4*)(mrow + I * 64 + tx * 4) = make_float4(res[0], res[1], res[2], res[3]);
    }
}

// =====================================================================
// Attention kernel: prefetched cp.async pipeline, ldmatrix frags,
// register softmax with __expf, dedicated O staging buffer
// =====================================================================
#define AT_Q 0
#define AT_K (AT_Q + 18432)
#define AT_V (AT_K + 18432)
#define AT_M (AT_V + 18432)              // f32 [64][68] = 17408
#define AT_B (AT_M + 17408)              // half [1800] = 3600 (+16 pad)
#define AT_O (AT_B + 3616)               // half [2][64][72] = 18432
#define SMEM_ATTN_BYTES (AT_O + 18432)   // 94752

__global__ __launch_bounds__(256)
void attn_kernel(const float* __restrict__ mult, const float* __restrict__ rel_table,
                 const __half* __restrict__ qkv, __half* __restrict__ obuf)
{
    extern __shared__ char smc[];
    float*  sMult  = (float*) (smc + AT_M);
    __half* sBiasH = (__half*)(smc + AT_B);
    __half* oStg   = (__half*)(smc + AT_O);

    const int b = blockIdx.x;
    const int tid = threadIdx.x;
    const int lane = tid & 31, w = tid >> 5;
    const int r = lane >> 2, cc = lane & 3;
    const int hs = w >> 2;
    const int m0 = (w & 3) * 16;
    const uint32_t sb = smem_u32(smc);

    const __half* qbase = qkv + (size_t)(b * 64) * 1536;

    auto issue_loads = [&](int hp) {
#pragma unroll
        for (int i = 0; i < 12; i++) {
            int c = tid + i * 256;
            int tensor = c >> 10;              // 0=q 1=k 2=v
            int rem = c & 1023;
            int hh = rem >> 9;
            int rr = rem & 511;
            int row = rr >> 3;
            int q8 = rr & 7;
            CP_ASYNC16(sb + AT_Q + tensor * 18432 + hh * 9216 + row * 144 + q8 * 16,
                       qbase + (size_t)row * 1536 + (hp * 2 + hh) * 64 + tensor * 512 + q8 * 8);
        }
        CP_COMMIT();
    };

    issue_loads(0);   // overlap hp0 loads with the prolog fills below

    for (int idx = tid; idx < 1024; idx += 256) {
        int row = idx >> 4;
        int c4 = (idx & 15) * 4;
        float4 v = *(const float4*)(mult + (size_t)b * 4096 + row * 64 + c4);
        *(float4*)(sMult + row * 68 + c4) = v;
    }
    for (int i = tid; i < 1800; i += 256)
        sBiasH[i] = __float2half(rel_table[i]);

    const uint32_t qOff = sb + AT_Q + hs * 9216 +
        ((m0 + (lane & 15)) * 72) * 2 + (lane >> 4) * 16;
    const uint32_t kOff = sb + AT_K + hs * 9216 +
        ((((lane >> 4) << 3) + (lane & 7)) * 72) * 2 + ((lane >> 3) & 1) * 16;
    const uint32_t vOff = sb + AT_V + hs * 9216 + (lane & 15) * 144;

    for (int hp = 0; hp < 4; hp++) {
        const int h = hp * 2 + hs;
        CP_WAIT0();
        __syncthreads();

        // ---- S = q @ k^T ----
        float acc[8][4];
#pragma unroll
        for (int nt = 0; nt < 8; nt++)
#pragma unroll
            for (int e = 0; e < 4; e++) acc[nt][e] = 0.f;
#pragma unroll
        for (int kt = 0; kt < 4; kt++) {
            uint32_t af[4], bf[8][2];
            LDSM_X4(af[0], af[1], af[2], af[3], qOff + kt * 32);
#pragma unroll
            for (int p = 0; p < 4; p++) {
                uint32_t r0, r1, r2, r3;
                LDSM_X4(r0, r1, r2, r3, kOff + p * 16 * 144 + kt * 32);
                bf[2 * p][0] = r0;     bf[2 * p][1] = r1;
                bf[2 * p + 1][0] = r2; bf[2 * p + 1][1] = r3;
            }
#pragma unroll
            for (int nt = 0; nt < 8; nt++)
                mma_f16(acc[nt], af, bf[nt]);
        }

        // ---- logits = s*mult + bias ----
        const int I0 = m0 + r, I1 = I0 + 8;
#pragma unroll
        for (int nt = 0; nt < 8; nt++) {
            int J = nt * 8 + 2 * cc;
            float2 mv0 = *(const float2*)(sMult + I0 * 68 + J);
            float2 mv1 = *(const float2*)(sMult + I1 * 68 + J);
            int dy0 = (I0 >> 3), dy1 = (I1 >> 3);
            int jy = (J >> 3);
            int dxa = (I0 & 7) - (J & 7) + 7;
            acc[nt][0] = acc[nt][0] * mv0.x + __half2float(sBiasH[((dy0 - jy + 7) * 15 + dxa) * 8 + h]);
            acc[nt][1] = acc[nt][1] * mv0.y + __half2float(sBiasH[((dy0 - jy + 7) * 15 + dxa - 1) * 8 + h]);
            acc[nt][2] = acc[nt][2] * mv1.x + __half2float(sBiasH[((dy1 - jy + 7) * 15 + dxa) * 8 + h]);
            acc[nt][3] = acc[nt][3] * mv1.y + __half2float(sBiasH[((dy1 - jy + 7) * 15 + dxa - 1) * 8 + h]);
        }

        // ---- register softmax (__expf) ----
        float mx0 = -1e30f, mx1 = -1e30f;
#pragma unroll
        for (int nt = 0; nt < 8; nt++) {
            mx0 = fmaxf(mx0, fmaxf(acc[nt][0], acc[nt][1]));
            mx1 = fmaxf(mx1, fmaxf(acc[nt][2], acc[nt][3]));
        }
        mx0 = fmaxf(mx0, __shfl_xor_sync(0xffffffffu, mx0, 1));
        mx0 = fmaxf(mx0, __shfl_xor_sync(0xffffffffu, mx0, 2));
        mx1 = fmaxf(mx1, __shfl_xor_sync(0xffffffffu, mx1, 1));
        mx1 = fmaxf(mx1, __shfl_xor_sync(0xffffffffu, mx1, 2));
        float s0 = 0.f, s1 = 0.f;
#pragma unroll
        for (int nt = 0; nt < 8; nt++) {
            acc[nt][0] = __expf(acc[nt][0] - mx0); s0 += acc[nt][0];
            acc[nt][1] = __expf(acc[nt][1] - mx0); s0 += acc[nt][1];
            acc[nt][2] = __expf(acc[nt][2] - mx1); s1 += acc[nt][2];
            acc[nt][3] = __expf(acc[nt][3] - mx1); s1 += acc[nt][3];
        }
        s0 += __shfl_xor_sync(0xffffffffu, s0, 1);
        s0 += __shfl_xor_sync(0xffffffffu, s0, 2);
        s1 += __shfl_xor_sync(0xffffffffu, s1, 1);
        s1 += __shfl_xor_sync(0xffffffffu, s1, 2);
        const float inv0 = 1.0f / s0, inv1 = 1.0f / s1;

        // ---- pack P into A-fragments ----
        uint32_t pa[4][4];
#pragma unroll
        for (int kt = 0; kt < 4; kt++) {
            __half2 h0 = __floats2half2_rn(acc[2 * kt][0] * inv0, acc[2 * kt][1] * inv0);
            __half2 h1 = __floats2half2_rn(acc[2 * kt][2] * inv1, acc[2 * kt][3] * inv1);
            __half2 h2 = __floats2half2_rn(acc[2 * kt + 1][0] * inv0, acc[2 * kt + 1][1] * inv0);
            __half2 h3 = __floats2half2_rn(acc[2 * kt + 1][2] * inv1, acc[2 * kt + 1][3] * inv1);
            pa[kt][0] = *(uint32_t*)&h0;
            pa[kt][1] = *(uint32_t*)&h1;
            pa[kt][2] = *(uint32_t*)&h2;
            pa[kt][3] = *(uint32_t*)&h3;
        }

        // ---- O = P @ V ----
        float oacc[8][4];
#pragma unroll
        for (int nt = 0; nt < 8; nt++)
#pragma unroll
            for (int e = 0; e < 4; e++) oacc[nt][e] = 0.f;
#pragma unroll
        for (int kt = 0; kt < 4; kt++) {
#pragma unroll
            for (int nt = 0; nt < 8; nt++) {
                uint32_t b0, b1;
                LDSM_X2T(b0, b1, vOff + kt * 2304 + nt * 16);
                uint32_t bf[2] = { b0, b1 };
                mma_f16(oacc[nt], pa[kt], bf);
            }
        }

        // all warps done reading q/k/v -> prefetch next head pair
        __syncthreads();
        if (hp + 1 < 4) issue_loads(hp + 1);

        // ---- stage O, then coalesced write (overlaps the async loads) ----
        {
            __half* stg = oStg + hs * 4608;
#pragma unroll
            for (int nt = 0; nt < 8; nt++) {
                int col = nt * 8 + 2 * cc;
                *(__half2*)(stg + I0 * 72 + col) =
                    __floats2half2_rn(oacc[nt][0], oacc[nt][1]);
                *(__half2*)(stg + I1 * 72 + col) =
                    __floats2half2_rn(oacc[nt][2], oacc[nt][3]);
            }
        }
        __syncthreads();
#pragma unroll
        for (int i = 0; i < 4; i++) {
            int idx = tid + i * 256;
            int hh = idx >> 9;
            int rem = idx & 511;
            int row = rem >> 3;
            int c8 = (rem & 7) * 8;
            float4 v = *(const float4*)(oStg + hh * 4608 + row * 72 + c8);
            *(float4*)(obuf + (size_t)(b * 64 + row) * 512 + (hp * 2 + hh) * 64 + c8) = v;
        }
    }
}

// =====================================================================
extern "C" void kernel_launch(void* const* d_in, const int* in_sizes, int n_in,
                              void* d_out, int out_size)
{
    const float* x      = (const float*)d_in[0];
    const float* dino   = (const float*)d_in[1];
    const float* point  = (const float*)d_in[2];
    /* d_in[3] color_feature: unused by reference */
    const float* sdf    = (const float*)d_in[4];
    const float* normal = (const float*)d_in[5];
    const float* smask  = (const float*)d_in[6];
    const float* cmask  = (const float*)d_in[7];
    const float* wq     = (const float*)d_in[8];
    const float* bq     = (const float*)d_in[9];
    const float* wkv    = (const float*)d_in[10];
    const float* bkv    = (const float*)d_in[11];
    const float* rel    = (const float*)d_in[12];
    const float* wproj  = (const float*)d_in[13];
    const float* bproj  = (const float*)d_in[14];
    float* out = (float*)d_out;

    __half *qkvh, *oh, *xh, *wh;
    float *mbuf, *gb;
    cudaGetSymbolAddress((void**)&qkvh, g_qkvh);
    cudaGetSymbolAddress((void**)&mbuf, g_mult);
    cudaGetSymbolAddress((void**)&oh, g_oh);
    cudaGetSymbolAddress((void**)&xh, g_xh);
    cudaGetSymbolAddress((void**)&wh, g_wh);
    cudaGetSymbolAddress((void**)&gb, g_bias);

    cudaFuncSetAttribute(mult_kernel, cudaFuncAttributeMaxDynamicSharedMemorySize, SMEM_MULT_BYTES);
    cudaFuncSetAttribute(attn_kernel, cudaFuncAttributeMaxDynamicSharedMemorySize, SMEM_ATTN_BYTES);
    cudaFuncSetAttribute(gemm_f16<1>, cudaFuncAttributeMaxDynamicSharedMemorySize, SMEM_GEMM_BYTES);
    cudaFuncSetAttribute(gemm_f16<0>, cudaFuncAttributeMaxDynamicSharedMemorySize, SMEM_GEMM_BYTES);

    dim3 blk(256);

    conv_kernel<<<1184, 256>>>(x, xh, (MROWS * DIM) / 4);
    wconv_kernel<<<1024, 256>>>(wq, wkv, wproj, bq, bkv, gb, wh);

    gemm_f16<1><<<dim3(6, MROWS / 128), blk, SMEM_GEMM_BYTES>>>(
        xh, wh, gb, qkvh, 1536);
    mult_kernel<<<NB, blk, SMEM_MULT_BYTES>>>(dino, point, sdf, normal, smask, cmask, mbuf);
    attn_kernel<<<NB, blk, SMEM_ATTN_BYTES>>>(mbuf, rel, qkvh, oh);
    gemm_f16<0><<<dim3(2, MROWS / 128), blk, SMEM_GEMM_BYTES>>>(
        oh, wh + 1536 * 512, bproj, out, 512);
}

// round 14
// speedup vs baseline: 1.5117x; 1.5117x over previous
#include <cuda_runtime.h>
#include <cuda_fp16.h>
#include <math.h>
#include <stdint.h>

#define NTOK 64
#define DIM 512
#define HEADS 8
#define NB 2048
#define MROWS (NB * NTOK)   // 131072
#define SCALE 0.125f
#define KDIM 512

// ---------------- scratch (device globals; no allocation) ----------------
static __device__ __half g_qkvh[(size_t)MROWS * 1536];  // q(scaled)|k|v  (half)
static __device__ float  g_mult[(size_t)NB * NTOK * NTOK];
static __device__ __half g_oh[(size_t)MROWS * DIM];     // attn out (half)
static __device__ __half g_xh[(size_t)MROWS * DIM];     // x  (half)
static __device__ __half g_wh[(size_t)2048 * 512];      // wq*SCALE|wkv|wproj (half)
static __device__ float  g_bias[1536];                  // SCALE*bq | bkv

__device__ __forceinline__ uint32_t smem_u32(const void* p) {
    uint32_t a;
    asm("{ .reg .u64 t; cvta.to.shared.u64 t, %1; cvt.u32.u64 %0, t; }" : "=r"(a) : "l"(p));
    return a;
}
#define CP_ASYNC16(dst, src) \
    asm volatile("cp.async.cg.shared.global [%0], [%1], 16;" :: "r"(dst), "l"(src) : "memory")
#define CP_COMMIT() asm volatile("cp.async.commit_group;" ::: "memory")
#define CP_WAIT2()  asm volatile("cp.async.wait_group 2;" ::: "memory")
#define CP_WAIT0()  asm volatile("cp.async.wait_group 0;" ::: "memory")

#define LDSM_X4(r0, r1, r2, r3, a) \
    asm volatile("ldmatrix.sync.aligned.m8n8.x4.shared.b16 {%0,%1,%2,%3}, [%4];" \
                 : "=r"(r0), "=r"(r1), "=r"(r2), "=r"(r3) : "r"(a))
#define LDSM_X2T(r0, r1, a) \
    asm volatile("ldmatrix.sync.aligned.m8n8.x2.trans.shared.b16 {%0,%1}, [%2];" \
                 : "=r"(r0), "=r"(r1) : "r"(a))

__device__ __forceinline__ void mma_f16(float* d, const uint32_t* a, const uint32_t* b) {
    asm volatile(
        "mma.sync.aligned.m16n8k16.row.col.f32.f16.f16.f32 "
        "{%0,%1,%2,%3}, {%4,%5,%6,%7}, {%8,%9}, {%0,%1,%2,%3};"
        : "+f"(d[0]), "+f"(d[1]), "+f"(d[2]), "+f"(d[3])
        : "r"(a[0]), "r"(a[1]), "r"(a[2]), "r"(a[3]), "r"(b[0]), "r"(b[1]));
}

// ===================== conversions =====================
__global__ void conv_kernel(const float* __restrict__ in, __half* __restrict__ out, int n4)
{
    int i = blockIdx.x * blockDim.x + threadIdx.x;
    int stride = gridDim.x * blockDim.x;
    for (; i < n4; i += stride) {
        float4 v = ((const float4*)in)[i];
        __half2* o = (__half2*)out;
        o[2 * i]     = __floats2half2_rn(v.x, v.y);
        o[2 * i + 1] = __floats2half2_rn(v.z, v.w);
    }
}

__global__ void wconv_kernel(const float* __restrict__ wq, const float* __restrict__ wkv,
                             const float* __restrict__ wproj, const float* __restrict__ bq,
                             const float* __restrict__ bkv, float* __restrict__ gb,
                             __half* __restrict__ wh)
{
    int i = blockIdx.x * blockDim.x + threadIdx.x;
    float s = 1.0f;
    const float* src;
    int o;
    if (i < 65536)       { src = wq;    o = i;          s = SCALE; }
    else if (i < 196608) { src = wkv;   o = i - 65536; }
    else                 { src = wproj; o = i - 196608; }
    float4 v = ((const float4*)src)[o];
    __half2* out = (__half2*)wh;
    out[2 * i]     = __floats2half2_rn(v.x * s, v.y * s);
    out[2 * i + 1] = __floats2half2_rn(v.z * s, v.w * s);
    if (i < 384) {
        float4 bv;
        if (i < 128) {
            bv = ((const float4*)bq)[i];
            bv.x *= SCALE; bv.y *= SCALE; bv.z *= SCALE; bv.w *= SCALE;
        } else {
            bv = ((const float4*)bkv)[i - 128];
        }
        ((float4*)gb)[i] = bv;
    }
}

// =====================================================================
// fp16 mma GEMM with ldmatrix fragment loads: C = A @ B^T + bias
// CTA 128x256, 8 warps (2m x 4n) of 64x64; BK=64 halfs; 3-stage cp.async
// =====================================================================
#define BKH 64
#define HSTRIDE 72
#define STAGE_HALFS ((128 + 256) * HSTRIDE)
#define STAGE_BYTES (STAGE_HALFS * 2)
#define NSTAGE 3
#define SMEM_GEMM_BYTES (NSTAGE * STAGE_BYTES)
#define NCHUNK (KDIM / BKH)

template<int OUTH>
__global__ __launch_bounds__(256, 1)
void gemm_f16(const __half* __restrict__ A, const __half* __restrict__ B,
              const float* __restrict__ bias, void* __restrict__ Cv, long ldc)
{
    extern __shared__ char smc[];
    __half* smh = (__half*)smc;
    const int tid = threadIdx.x;
    const int lane = tid & 31;
    const int wid = tid >> 5;
    const int warp_m = wid & 1;
    const int warp_n = wid >> 1;
    const long m0 = (long)blockIdx.y * 128;
    const long n0 = (long)blockIdx.x * 256;

    const __half* Ag = A + m0 * KDIM;
    const __half* Bg = B + n0 * KDIM;
    const uint32_t sb = smem_u32(smc);

    auto copy_chunk = [&](int chunk, int s) {
        const int k0 = chunk * BKH;
        const uint32_t dstA = sb + s * STAGE_BYTES;
        const uint32_t dstB = dstA + 128 * HSTRIDE * 2;
#pragma unroll
        for (int i = 0; i < 4; i++) {
            int idx = tid + i * 256;
            int row = idx >> 3, q = idx & 7;
            CP_ASYNC16(dstA + row * (HSTRIDE * 2) + q * 16,
                       Ag + (long)row * KDIM + k0 + q * 8);
        }
#pragma unroll
        for (int i = 0; i < 8; i++) {
            int idx = tid + i * 256;
            int row = idx >> 3, q = idx & 7;
            CP_ASYNC16(dstB + row * (HSTRIDE * 2) + q * 16,
                       Bg + (long)row * KDIM + k0 + q * 8);
        }
        CP_COMMIT();
    };

    float acc[4][8][4];
#pragma unroll
    for (int mt = 0; mt < 4; mt++)
#pragma unroll
        for (int nt = 0; nt < 8; nt++)
#pragma unroll
            for (int e = 0; e < 4; e++) acc[mt][nt][e] = 0.f;

    copy_chunk(0, 0);
    copy_chunk(1, 1);
    copy_chunk(2, 2);

    const int r = lane >> 2;
    const int cc = lane & 3;
    const uint32_t aOff = ((warp_m * 64 + (lane & 15)) * HSTRIDE) * 2 + (lane >> 4) * 16;
    const uint32_t bOff = 128 * HSTRIDE * 2 +
        ((warp_n * 64 + ((lane >> 4) << 3) + (lane & 7)) * HSTRIDE) * 2 + ((lane >> 3) & 1) * 16;

    for (int c = 0; c < NCHUNK; c++) {
        const int s = c % NSTAGE;
        CP_WAIT2();
        __syncthreads();
        const uint32_t stA = sb + s * STAGE_BYTES;
        const uint32_t aL = stA + aOff;
        const uint32_t bL = stA + bOff;

#pragma unroll
        for (int k16 = 0; k16 < 4; k16++) {
            uint32_t af[4][4], bf[8][2];
#pragma unroll
            for (int mt = 0; mt < 4; mt++)
                LDSM_X4(af[mt][0], af[mt][1], af[mt][2], af[mt][3],
                        aL + mt * 16 * HSTRIDE * 2 + k16 * 32);
#pragma unroll
            for (int p = 0; p < 4; p++) {
                uint32_t r0, r1, r2, r3;
                LDSM_X4(r0, r1, r2, r3, bL + p * 16 * HSTRIDE * 2 + k16 * 32);
                bf[2 * p][0] = r0;     bf[2 * p][1] = r1;
                bf[2 * p + 1][0] = r2; bf[2 * p + 1][1] = r3;
            }
#pragma unroll
            for (int mt = 0; mt < 4; mt++)
#pragma unroll
                for (int nt = 0; nt < 8; nt++)
                    mma_f16(acc[mt][nt], af[mt], bf[nt]);
        }
        __syncthreads();
        if (c + 3 < NCHUNK) copy_chunk(c + 3, s);
        else CP_COMMIT();
    }

    if (OUTH) {
        __half* se = smh;
        const int row0 = warp_m * 64;
        const int col0 = warp_n * 64;
#pragma unroll
        for (int mt = 0; mt < 4; mt++)
#pragma unroll
            for (int nt = 0; nt < 8; nt++) {
                int rr = row0 + mt * 16 + r;
                int cb = col0 + nt * 8 + 2 * cc;
                float2 bv = *(const float2*)(bias + n0 + cb);
                *(__half2*)(se + rr * 264 + cb) =
                    __floats2half2_rn(acc[mt][nt][0] + bv.x, acc[mt][nt][1] + bv.y);
                *(__half2*)(se + (rr + 8) * 264 + cb) =
                    __floats2half2_rn(acc[mt][nt][2] + bv.x, acc[mt][nt][3] + bv.y);
            }
        __syncthreads();
        __half* Ch = (__half*)Cv;
#pragma unroll
        for (int i = 0; i < 16; i++) {
            int idx = tid + i * 256;
            int row = idx >> 5;
            int c8 = (idx & 31) * 8;
            float4 v = *(const float4*)(se + row * 264 + c8);
            *(float4*)(Ch + (m0 + row) * ldc + n0 + c8) = v;
        }
    } else {
        float* se = (float*)smc;
        const int row0 = warp_m * 64;
        const int col0 = warp_n * 64;
#pragma unroll
        for (int mt = 0; mt < 4; mt++)
#pragma unroll
            for (int nt = 0; nt < 8; nt++) {
                int rr = row0 + mt * 16 + r;
                int cb = col0 + nt * 8 + 2 * cc;
                float2 bv = *(const float2*)(bias + n0 + cb);
                *(float2*)(se + rr * 264 + cb) =
                    make_float2(acc[mt][nt][0] + bv.x, acc[mt][nt][1] + bv.y);
                *(float2*)(se + (rr + 8) * 264 + cb) =
                    make_float2(acc[mt][nt][2] + bv.x, acc[mt][nt][3] + bv.y);
            }
        __syncthreads();
        float* Cf = (float*)Cv;
#pragma unroll
        for (int i = 0; i < 32; i++) {
            int idx = tid + i * 256;
            int row = idx >> 6;
            int c4 = (idx & 63) * 4;
            float4 v = *(const float4*)(se + row * 264 + c4);
            *(float4*)(Cf + (m0 + row) * ldc + n0 + c4) = v;
        }
    }
}

// =====================================================================
// Correlation-map kernel: ALL THREE Grams (dino / sdf / cluster) via fp16 mma
// =====================================================================
#define MH_STRIDE 104
#define MK_D   0                       // half [2][64][104] = 26624 B; later overlaid by sG3
#define MK_G   (MK_D + 26624)          // float [64][68]
#define MK_G2  (MK_G + 17408)          // float [64][68]
#define MK_SF  (MK_G2 + 17408)         // half [64][24]  sdf
#define MK_SCL (MK_SF + 3072)          // half [64][24]  cluster (k8-15 zero)
#define MK_RND (MK_SCL + 3072)
#define MK_RNS (MK_RND + 256)
#define MK_SP  (MK_RNS + 256)
#define MK_SN  (MK_SP + 768)
#define MK_SC  (MK_SN + 768)
#define SMEM_MULT_BYTES (MK_SC + 256)  // 69888

__global__ __launch_bounds__(256)
void mult_kernel(const float* __restrict__ dino, const float* __restrict__ point,
                 const float* __restrict__ sdf, const float* __restrict__ normal,
                 const float* __restrict__ smask, const float* __restrict__ cmask,
                 float* __restrict__ mout)
{
    extern __shared__ char smc[];
    __half* sDh  = (__half*)(smc + MK_D);
    float* sG3   = (float*)(smc + MK_D);    // overlays sDh after dino loop
    float* sG    = (float*)(smc + MK_G);
    float* sG2   = (float*)(smc + MK_G2);
    __half* sfh  = (__half*)(smc + MK_SF);
    __half* sclh = (__half*)(smc + MK_SCL);
    float* rnD   = (float*)(smc + MK_RND);
    float* rnS   = (float*)(smc + MK_RNS);
    float* sp    = (float*)(smc + MK_SP);
    float* sn    = (float*)(smc + MK_SN);
    float* scode = (float*)(smc + MK_SC);

    const int b = blockIdx.x;
    const int tid = threadIdx.x;
    const int lane = tid & 31, w = tid >> 5;
    const int r = lane >> 2, cc = lane & 3;
    const int m0 = (w & 3) * 16, n0 = (w >> 2) * 32;

    // sdf -> half [64][24]
    {
        int row = tid >> 2;
        int kg = (tid & 3) * 4;
        float4 v = *(const float4*)(sdf + (size_t)b * 1024 + row * 16 + kg);
        *(__half2*)(sfh + row * 24 + kg)     = __floats2half2_rn(v.x, v.y);
        *(__half2*)(sfh + row * 24 + kg + 2) = __floats2half2_rn(v.z, v.w);
    }
    // cluster -> half [64][24], k8..15 zeroed
    if (tid < 128) {
        int row = tid >> 1;
        int c4 = (tid & 1) * 4;
        float4 v = *(const float4*)(cmask + (size_t)b * 512 + row * 8 + c4);
        *(__half2*)(sclh + row * 24 + c4)     = __floats2half2_rn(v.x, v.y);
        *(__half2*)(sclh + row * 24 + c4 + 2) = __floats2half2_rn(v.z, v.w);
        *(uint2*)(sclh + row * 24 + 8 + c4) = make_uint2(0u, 0u);
    }
    if (tid < 192) {
        sp[tid] = point[(size_t)b * 192 + tid];
        sn[tid] = normal[(size_t)b * 192 + tid];
    }
    if (tid < 64)
        scode[tid] = (smask[(size_t)b * 64 + tid] < 0.1f) ? 1.f : 2.f;

    const float* dg = dino + (size_t)b * 64 * 384;
    auto load_chunk = [&](int kc, int buf) {
        __half* dst = sDh + buf * 64 * MH_STRIDE;
        const int k0 = kc * 96;
#pragma unroll
        for (int i = 0; i < 6; i++) {
            int idx = tid + i * 256;
            int row = idx / 24;
            int q = idx % 24;
            float4 v = *(const float4*)(dg + row * 384 + k0 + q * 4);
            *(__half2*)(dst + row * MH_STRIDE + q * 4)     = __floats2half2_rn(v.x, v.y);
            *(__half2*)(dst + row * MH_STRIDE + q * 4 + 2) = __floats2half2_rn(v.z, v.w);
        }
    };

    float gacc[4][4];
#pragma unroll
    for (int i = 0; i < 4; i++)
#pragma unroll
        for (int j = 0; j < 4; j++) gacc[i][j] = 0.f;

    load_chunk(0, 0);
    __syncthreads();
    for (int c = 0; c < 4; c++) {
        if (c + 1 < 4) load_chunk(c + 1, (c + 1) & 1);
        const __half* buf = sDh + (c & 1) * 64 * MH_STRIDE;
        const __half* aB = buf + (m0 + r) * MH_STRIDE + 2 * cc;
#pragma unroll
        for (int ks = 0; ks < 6; ks++) {
            uint32_t af[4];
            const __half* ap = aB + ks * 16;
            af[0] = *(const uint32_t*)(ap);
            af[1] = *(const uint32_t*)(ap + 8 * MH_STRIDE);
            af[2] = *(const uint32_t*)(ap + 8);
            af[3] = *(const uint32_t*)(ap + 8 * MH_STRIDE + 8);
#pragma unroll
            for (int nt = 0; nt < 4; nt++) {
                const __half* bp = buf + (n0 + nt * 8 + r) * MH_STRIDE + 2 * cc + ks * 16;
                uint32_t bf[2] = { *(const uint32_t*)(bp), *(const uint32_t*)(bp + 8) };
                mma_f16(gacc[nt], af, bf);
            }
        }
        __syncthreads();
    }

    // sdf + cluster Grams: one k16 step each
    float s2[4][4], s3[4][4];
#pragma unroll
    for (int i = 0; i < 4; i++)
#pragma unroll
        for (int j = 0; j < 4; j++) { s2[i][j] = 0.f; s3[i][j] = 0.f; }
    {
        const __half* ap2 = sfh + (m0 + r) * 24 + 2 * cc;
        uint32_t af2[4] = { *(const uint32_t*)(ap2), *(const uint32_t*)(ap2 + 8 * 24),
                            *(const uint32_t*)(ap2 + 8), *(const uint32_t*)(ap2 + 8 * 24 + 8) };
        const __half* ap3 = sclh + (m0 + r) * 24 + 2 * cc;
        uint32_t af3[4] = { *(const uint32_t*)(ap3), *(const uint32_t*)(ap3 + 8 * 24),
                            *(const uint32_t*)(ap3 + 8), *(const uint32_t*)(ap3 + 8 * 24 + 8) };
#pragma unroll
        for (int nt = 0; nt < 4; nt++) {
            const __half* bp2 = sfh + (n0 + nt * 8 + r) * 24 + 2 * cc;
            uint32_t bf2[2] = { *(const uint32_t*)(bp2), *(const uint32_t*)(bp2 + 8) };
            mma_f16(s2[nt], af2, bf2);
            const __half* bp3 = sclh + (n0 + nt * 8 + r) * 24 + 2 * cc;
            uint32_t bf3[2] = { *(const uint32_t*)(bp3), *(const uint32_t*)(bp3 + 8) };
            mma_f16(s3[nt], af3, bf3);
        }
    }

    // write all Gram fragments (sG3 overlays sDh — all dino reads done)
#pragma unroll
    for (int nt = 0; nt < 4; nt++) {
        int col = n0 + nt * 8 + 2 * cc;
        int I0 = m0 + r, I1 = I0 + 8;
        sG[I0 * 68 + col]      = gacc[nt][0];
        sG[I0 * 68 + col + 1]  = gacc[nt][1];
        sG[I1 * 68 + col]      = gacc[nt][2];
        sG[I1 * 68 + col + 1]  = gacc[nt][3];
        sG2[I0 * 68 + col]     = s2[nt][0];
        sG2[I0 * 68 + col + 1] = s2[nt][1];
        sG2[I1 * 68 + col]     = s2[nt][2];
        sG2[I1 * 68 + col + 1] = s2[nt][3];
        sG3[I0 * 68 + col]     = s3[nt][0];
        sG3[I0 * 68 + col + 1] = s3[nt][1];
        sG3[I1 * 68 + col]     = s3[nt][2];
        sG3[I1 * 68 + col + 1] = s3[nt][3];
    }
    __syncthreads();

    if (tid < 64) {
        float nn = fminf(fmaxf(sqrtf(fmaxf(sG[tid * 68 + tid], 0.f)), 1e-20f), 1e10f);
        rnD[tid] = 1.0f / nn;
        nn = fminf(fmaxf(sqrtf(fmaxf(sG2[tid * 68 + tid], 0.f)), 1e-20f), 1e10f);
        rnS[tid] = 1.0f / nn;
    }
    __syncthreads();

    const int tx = tid & 15, ty = tid >> 4;
    float* mrow = mout + (size_t)b * 4096;
#pragma unroll
    for (int i = 0; i < 4; i++) {
        int I = ty * 4 + i;
        float ga[4], g2a[4], g3a[4], res[4];
        *(float4*)ga  = *(const float4*)(sG  + I * 68 + tx * 4);
        *(float4*)g2a = *(const float4*)(sG2 + I * 68 + tx * 4);
        *(float4*)g3a = *(const float4*)(sG3 + I * 68 + tx * 4);
#pragma unroll
        for (int j = 0; j < 4; j++) {
            int J = tx * 4 + j;
            float dmap = fminf(fmaxf(ga[j] * rnD[I] * rnD[J], 0.f), 1e10f);
            float smap = 1.f - fminf(fmaxf(g2a[j] * rnS[I] * rnS[J], 0.f), 1.f);
            float P1 = 0.f, P2 = 0.f;
#pragma unroll
            for (int d = 0; d < 3; d++) {
                float diff = sp[I * 3 + d] - sp[J * 3 + d];
                P1 += diff * sn[I * 3 + d];
                P2 += diff * sn[J * 3 + d];
            }
            float plane = expf(-0.5f * (fabsf(P1) + fabsf(P2)));
            float mm = (scode[I] * scode[J] == 2.f) ? 1.f : 0.2f;
            res[j] = dmap * smap * plane * g3a[j] * mm;
        }
        *(float4*)(mrow + I * 64 + tx * 4) = make_float4(res[0], res[1], res[2], res[3]);
    }
}

// =====================================================================
// Attention kernel: cp.async loads, ldmatrix frags, register softmax,
// smem-staged coalesced O stores
// =====================================================================
#define AT_Q 0
#define AT_K (AT_Q + 2*64*72*2)          // 18432 spacing
#define AT_V (AT_K + 2*64*72*2)
#define AT_M (AT_V + 2*64*72*2)          // f32 [64][68]
#define AT_B (AT_M + 64*68*4)            // half [1800]
#define SMEM_ATTN_BYTES (AT_B + 1800*2)  // 76304

__global__ __launch_bounds__(256)
void attn_kernel(const float* __restrict__ mult, const float* __restrict__ rel_table,
                 const __half* __restrict__ qkv, __half* __restrict__ obuf)
{
    extern __shared__ char smc[];
    __half* qB     = (__half*)(smc + AT_Q);   // [2][64][72]
    __half* vB     = (__half*)(smc + AT_V);   // [2][64][72] natural
    float*  sMult  = (float*) (smc + AT_M);
    __half* sBiasH = (__half*)(smc + AT_B);

    const int b = blockIdx.x;
    const int tid = threadIdx.x;
    const int lane = tid & 31, w = tid >> 5;
    const int r = lane >> 2, cc = lane & 3;
    const int hs = w >> 2;
    const int m0 = (w & 3) * 16;
    const uint32_t sb = smem_u32(smc);

    for (int idx = tid; idx < 1024; idx += 256) {
        int row = idx >> 4;
        int c4 = (idx & 15) * 4;
        float4 v = *(const float4*)(mult + (size_t)b * 4096 + row * 64 + c4);
        *(float4*)(sMult + row * 68 + c4) = v;
    }
    for (int i = tid; i < 1800; i += 256)
        sBiasH[i] = __float2half(rel_table[i]);

    const __half* qbase = qkv + (size_t)(b * 64) * 1536;
    // per-lane ldmatrix bases (head-half fixed per warp)
    const uint32_t qOff = sb + AT_Q + hs * 9216 +
        ((m0 + (lane & 15)) * 72) * 2 + (lane >> 4) * 16;
    const uint32_t kOff = sb + AT_K + hs * 9216 +
        ((((lane >> 4) << 3) + (lane & 7)) * 72) * 2 + ((lane >> 3) & 1) * 16;
    const uint32_t vOff = sb + AT_V + hs * 9216 + (lane & 15) * 144;

    for (int hp = 0; hp < 4; hp++) {
        const int h = hp * 2 + hs;
        // cp.async q,k,v for both heads: 3072 x 16B chunks
#pragma unroll
        for (int i = 0; i < 12; i++) {
            int c = tid + i * 256;
            int tensor = c >> 10;              // 0=q 1=k 2=v
            int rem = c & 1023;
            int hh = rem >> 9;
            int rr = rem & 511;
            int row = rr >> 3;
            int q8 = rr & 7;
            CP_ASYNC16(sb + AT_Q + tensor * 18432 + hh * 9216 + row * 144 + q8 * 16,
                       qbase + (size_t)row * 1536 + (hp * 2 + hh) * 64 + tensor * 512 + q8 * 8);
        }
        CP_COMMIT();
        CP_WAIT0();
        __syncthreads();

        // ---- S = q @ k^T via ldmatrix frags ----
        float acc[8][4];
#pragma unroll
        for (int nt = 0; nt < 8; nt++)
#pragma unroll
            for (int e = 0; e < 4; e++) acc[nt][e] = 0.f;
#pragma unroll
        for (int kt = 0; kt < 4; kt++) {
            uint32_t af[4], bf[8][2];
            LDSM_X4(af[0], af[1], af[2], af[3], qOff + kt * 32);
#pragma unroll
            for (int p = 0; p < 4; p++) {
                uint32_t r0, r1, r2, r3;
                LDSM_X4(r0, r1, r2, r3, kOff + p * 16 * 144 + kt * 32);
                bf[2 * p][0] = r0;     bf[2 * p][1] = r1;
                bf[2 * p + 1][0] = r2; bf[2 * p + 1][1] = r3;
            }
#pragma unroll
            for (int nt = 0; nt < 8; nt++)
                mma_f16(acc[nt], af, bf[nt]);
        }

        // ---- logits = s*mult + bias ----
        const int I0 = m0 + r, I1 = I0 + 8;
#pragma unroll
        for (int nt = 0; nt < 8; nt++) {
            int J = nt * 8 + 2 * cc;
            float2 mv0 = *(const float2*)(sMult + I0 * 68 + J);
            float2 mv1 = *(const float2*)(sMult + I1 * 68 + J);
            int dy0 = (I0 >> 3), dy1 = (I1 >> 3);
            int jy = (J >> 3);
            int dxa = (I0 & 7) - (J & 7) + 7;
            acc[nt][0] = acc[nt][0] * mv0.x + __half2float(sBiasH[((dy0 - jy + 7) * 15 + dxa) * 8 + h]);
            acc[nt][1] = acc[nt][1] * mv0.y + __half2float(sBiasH[((dy0 - jy + 7) * 15 + dxa - 1) * 8 + h]);
            acc[nt][2] = acc[nt][2] * mv1.x + __half2float(sBiasH[((dy1 - jy + 7) * 15 + dxa) * 8 + h]);
            acc[nt][3] = acc[nt][3] * mv1.y + __half2float(sBiasH[((dy1 - jy + 7) * 15 + dxa - 1) * 8 + h]);
        }

        // ---- register softmax ----
        float mx0 = -1e30f, mx1 = -1e30f;
#pragma unroll
        for (int nt = 0; nt < 8; nt++) {
            mx0 = fmaxf(mx0, fmaxf(acc[nt][0], acc[nt][1]));
            mx1 = fmaxf(mx1, fmaxf(acc[nt][2], acc[nt][3]));
        }
        mx0 = fmaxf(mx0, __shfl_xor_sync(0xffffffffu, mx0, 1));
        mx0 = fmaxf(mx0, __shfl_xor_sync(0xffffffffu, mx0, 2));
        mx1 = fmaxf(mx1, __shfl_xor_sync(0xffffffffu, mx1, 1));
        mx1 = fmaxf(mx1, __shfl_xor_sync(0xffffffffu, mx1, 2));
        float s0 = 0.f, s1 = 0.f;
#pragma unroll
        for (int nt = 0; nt < 8; nt++) {
            acc[nt][0] = expf(acc[nt][0] - mx0); s0 += acc[nt][0];
            acc[nt][1] = expf(acc[nt][1] - mx0); s0 += acc[nt][1];
            acc[nt][2] = expf(acc[nt][2] - mx1); s1 += acc[nt][2];
            acc[nt][3] = expf(acc[nt][3] - mx1); s1 += acc[nt][3];
        }
        s0 += __shfl_xor_sync(0xffffffffu, s0, 1);
        s0 += __shfl_xor_sync(0xffffffffu, s0, 2);
        s1 += __shfl_xor_sync(0xffffffffu, s1, 1);
        s1 += __shfl_xor_sync(0xffffffffu, s1, 2);
        const float inv0 = 1.0f / s0, inv1 = 1.0f / s1;

        // ---- pack P into A-fragments ----
        uint32_t pa[4][4];
#pragma unroll
        for (int kt = 0; kt < 4; kt++) {
            __half2 h0 = __floats2half2_rn(acc[2 * kt][0] * inv0, acc[2 * kt][1] * inv0);
            __half2 h1 = __floats2half2_rn(acc[2 * kt][2] * inv1, acc[2 * kt][3] * inv1);
            __half2 h2 = __floats2half2_rn(acc[2 * kt + 1][0] * inv0, acc[2 * kt + 1][1] * inv0);
            __half2 h3 = __floats2half2_rn(acc[2 * kt + 1][2] * inv1, acc[2 * kt + 1][3] * inv1);
            pa[kt][0] = *(uint32_t*)&h0;
            pa[kt][1] = *(uint32_t*)&h1;
            pa[kt][2] = *(uint32_t*)&h2;
            pa[kt][3] = *(uint32_t*)&h3;
        }

        // ---- O = P @ V (V natural, B-frags via ldmatrix.trans) ----
        float oacc[8][4];
#pragma unroll
        for (int nt = 0; nt < 8; nt++)
#pragma unroll
            for (int e = 0; e < 4; e++) oacc[nt][e] = 0.f;
#pragma unroll
        for (int kt = 0; kt < 4; kt++) {
#pragma unroll
            for (int nt = 0; nt < 8; nt++) {
                uint32_t b0, b1;
                LDSM_X2T(b0, b1, vOff + kt * 2304 + nt * 16);
                uint32_t bf[2] = { b0, b1 };
                mma_f16(oacc[nt], pa[kt], bf);
            }
        }

        // ---- stage O into qB (q consumed), then coalesced write ----
        __syncthreads();
        {
            __half* stg = qB + hs * 4608;
#pragma unroll
            for (int nt = 0; nt < 8; nt++) {
                int col = nt * 8 + 2 * cc;
                *(__half2*)(stg + I0 * 72 + col) =
                    __floats2half2_rn(oacc[nt][0], oacc[nt][1]);
                *(__half2*)(stg + I1 * 72 + col) =
                    __floats2half2_rn(oacc[nt][2], oacc[nt][3]);
            }
        }
        __syncthreads();
#pragma unroll
        for (int i = 0; i < 4; i++) {
            int idx = tid + i * 256;          // 0..1023
            int hh = idx >> 9;
            int rem = idx & 511;
            int row = rem >> 3;
            int c8 = (rem & 7) * 8;
            float4 v = *(const float4*)(qB + hh * 4608 + row * 72 + c8);
            *(float4*)(obuf + (size_t)(b * 64 + row) * 512 + (hp * 2 + hh) * 64 + c8) = v;
        }
        __syncthreads();
    }
}

// =====================================================================
extern "C" void kernel_launch(void* const* d_in, const int* in_sizes, int n_in,
                              void* d_out, int out_size)
{
    const float* x      = (const float*)d_in[0];
    const float* dino   = (const float*)d_in[1];
    const float* point  = (const float*)d_in[2];
    /* d_in[3] color_feature: unused by reference */
    const float* sdf    = (const float*)d_in[4];
    const float* normal = (const float*)d_in[5];
    const float* smask  = (const float*)d_in[6];
    const float* cmask  = (const float*)d_in[7];
    const float* wq     = (const float*)d_in[8];
    const float* bq     = (const float*)d_in[9];
    const float* wkv    = (const float*)d_in[10];
    const float* bkv    = (const float*)d_in[11];
    const float* rel    = (const float*)d_in[12];
    const float* wproj  = (const float*)d_in[13];
    const float* bproj  = (const float*)d_in[14];
    float* out = (float*)d_out;

    __half *qkvh, *oh, *xh, *wh;
    float *mbuf, *gb;
    cudaGetSymbolAddress((void**)&qkvh, g_qkvh);
    cudaGetSymbolAddress((void**)&mbuf, g_mult);
    cudaGetSymbolAddress((void**)&oh, g_oh);
    cudaGetSymbolAddress((void**)&xh, g_xh);
    cudaGetSymbolAddress((void**)&wh, g_wh);
    cudaGetSymbolAddress((void**)&gb, g_bias);

    cudaFuncSetAttribute(mult_kernel, cudaFuncAttributeMaxDynamicSharedMemorySize, SMEM_MULT_BYTES);
    cudaFuncSetAttribute(attn_kernel, cudaFuncAttributeMaxDynamicSharedMemorySize, SMEM_ATTN_BYTES);
    cudaFuncSetAttribute(gemm_f16<1>, cudaFuncAttributeMaxDynamicSharedMemorySize, SMEM_GEMM_BYTES);
    cudaFuncSetAttribute(gemm_f16<0>, cudaFuncAttributeMaxDynamicSharedMemorySize, SMEM_GEMM_BYTES);

    dim3 blk(256);

    // conversions
    conv_kernel<<<1184, 256>>>(x, xh, (MROWS * DIM) / 4);
    wconv_kernel<<<1024, 256>>>(wq, wkv, wproj, bq, bkv, gb, wh);

    // qkv = x @ [SCALE*wq | wkv]^T + [SCALE*bq | bkv]  (half out)
    gemm_f16<1><<<dim3(6, MROWS / 128), blk, SMEM_GEMM_BYTES>>>(
        xh, wh, gb, qkvh, 1536);
    // correlation maps
    mult_kernel<<<NB, blk, SMEM_MULT_BYTES>>>(dino, point, sdf, normal, smask, cmask, mbuf);
    // attention (half in, half out)
    attn_kernel<<<NB, blk, SMEM_ATTN_BYTES>>>(mbuf, rel, qkvh, oh);
    // out = o @ wproj^T + bproj  (float out)
    gemm_f16<0><<<dim3(2, MROWS / 128), blk, SMEM_GEMM_BYTES>>>(
        oh, wh + 1536 * 512, bproj, out, 512);
}